// round 13
// baseline (speedup 1.0000x reference)
#include <cuda_runtime.h>
#include <math.h>
#include <stdint.h>

#define BB 2
#define TT 2048
#define CC 2048
#define HH 16
#define DD 128
#define NEGF -1000000000.0f

// Scratch (device globals — referenced ONLY from device code)
__device__ float g_qkv[(size_t)3 * BB * HH * TT * DD];  // [3][B][H][T][D]
__device__ float g_att[(size_t)BB * TT * CC];           // [B][T][C] (tf32-rounded)
__device__ float g_xc[(size_t)BB * TT * CC];            // x rounded to tf32
__device__ float g_wqc[(size_t)3 * CC * CC];            // Wqkv rounded
__device__ float g_woc[(size_t)CC * CC];                // Wout rounded
__device__ float g_cos[TT * 64];
__device__ float g_sin[TT * 64];

// ---------------------------------------------------------------------------
__device__ __forceinline__ uint32_t f2tf32(float x) {
    uint32_t r;
    asm volatile("cvt.rna.tf32.f32 %0, %1;\n" : "=r"(r) : "f"(x));
    return r;
}
__device__ __forceinline__ float rtf(float x) { return __uint_as_float(f2tf32(x)); }
__device__ __forceinline__ void cp_async16(void* smem, const void* gmem) {
    uint32_t s = (uint32_t)__cvta_generic_to_shared(smem);
    asm volatile("cp.async.cg.shared.global [%0], [%1], 16;\n" :: "r"(s), "l"(gmem));
}
__device__ __forceinline__ void mma_tf32(float4& d, const uint32_t a[4], const uint32_t b[2]) {
    asm volatile(
        "mma.sync.aligned.m16n8k8.row.col.f32.tf32.tf32.f32 "
        "{%0,%1,%2,%3}, {%4,%5,%6,%7}, {%8,%9}, {%0,%1,%2,%3};\n"
        : "+f"(d.x), "+f"(d.y), "+f"(d.z), "+f"(d.w)
        : "r"(a[0]), "r"(a[1]), "r"(a[2]), "r"(a[3]), "r"(b[0]), "r"(b[1]));
}

// ---------------------------------------------------------------------------
__global__ void rope_table_kernel() {   // 256 threads, 4 positions/block
    int t = blockIdx.x * 4 + (threadIdx.x >> 6);
    int d = threadIdx.x & 63;
    double inv = exp2(-((double)(2 * d) / 128.0) * log2(10000.0));
    float f = (float)t * (float)inv;
    g_cos[t * 64 + d] = cosf(f);
    g_sin[t * 64 + d] = sinf(f);
}

// Round to tf32-valued fp32 into device-global dst (resolved in device code)
template <int WHICH>
__global__ void cvt_tf32_kernel(const float* __restrict__ src, int n4) {
    float* dst = (WHICH == 0) ? g_xc : (WHICH == 1) ? g_wqc : g_woc;
    int i = blockIdx.x * blockDim.x + threadIdx.x;
    if (i < n4) {
        float4 v = ((const float4*)src)[i];
        v.x = rtf(v.x); v.y = rtf(v.y); v.z = rtf(v.z); v.w = rtf(v.w);
        ((float4*)dst)[i] = v;
    }
}

// ---------------------------------------------------------------------------
// tf32 mma.sync GEMM (NT), 2-stage cp.async, static 64KB smem (R10-proven
// mainloop).
// EPI==0: A=g_xc, W=g_wqc; epilogue stages the tile in smem, applies RoPE
//         (q,k) / identity (v) + tf32 rounding, writes g_qkv. Replaces the
//         separate rope_split kernel (bit-exact same math).
// EPI==1: A=g_att, W=g_woc, plain row-major store to out.
// ---------------------------------------------------------------------------
#define GBK 32
#define STAGE_F (128 * GBK)
#define PADW 132

__device__ __forceinline__ int sw_off(int row, int k) {
    return row * GBK + ((((k >> 2) ^ (row & 7)) << 2) | (k & 3));
}

template <int EPI>
__global__ void __launch_bounds__(256, 2) gemm_tf32(float* __restrict__ out) {
    __shared__ float smem_all[4 * STAGE_F];   // 64 KB: As|Bs during loop, stage after
    uint32_t* As = (uint32_t*)smem_all;               // [2][STAGE_F]
    uint32_t* Bs = (uint32_t*)smem_all + 2 * STAGE_F; // [2][STAGE_F]

    const float* A = (EPI == 0) ? (const float*)g_xc  : (const float*)g_att;
    const float* W = (EPI == 0) ? (const float*)g_wqc : (const float*)g_woc;
    const int K = CC;
    const int N = (EPI == 0) ? 3 * CC : CC;

    const int tid = threadIdx.x;
    const int m0 = blockIdx.y * 128, n0 = blockIdx.x * 128;

    const int wid = tid >> 5;
    const int lane = tid & 31;
    const int wm = wid & 3;
    const int wn = wid >> 2;
    const int g = lane >> 2;
    const int c = lane & 3;

    const int lr = tid >> 3;
    const int lc4 = tid & 7;

    float4 acc[2][8];
#pragma unroll
    for (int i = 0; i < 2; i++)
#pragma unroll
        for (int j = 0; j < 8; j++) acc[i][j] = make_float4(0.f, 0.f, 0.f, 0.f);

    const int NT = K / GBK;

    {
#pragma unroll
        for (int i = 0; i < 4; i++) {
            int r = lr + i * 32;
            int sw = (lc4 ^ (r & 7)) << 2;
            cp_async16(&As[r * GBK + sw], A + (size_t)(m0 + r) * K + lc4 * 4);
            cp_async16(&Bs[r * GBK + sw], W + (size_t)(n0 + r) * K + lc4 * 4);
        }
        asm volatile("cp.async.commit_group;\n");
    }

    for (int kt = 0; kt < NT; kt++) {
        int cur = kt & 1;
        if (kt + 1 < NT) {
            int nxt = cur ^ 1;
            int k0 = (kt + 1) * GBK;
#pragma unroll
            for (int i = 0; i < 4; i++) {
                int r = lr + i * 32;
                int sw = (lc4 ^ (r & 7)) << 2;
                cp_async16(&As[nxt * STAGE_F + r * GBK + sw], A + (size_t)(m0 + r) * K + k0 + lc4 * 4);
                cp_async16(&Bs[nxt * STAGE_F + r * GBK + sw], W + (size_t)(n0 + r) * K + k0 + lc4 * 4);
            }
        }
        asm volatile("cp.async.commit_group;\n");
        asm volatile("cp.async.wait_group 1;\n");
        __syncthreads();

        const uint32_t* as = As + cur * STAGE_F;
        const uint32_t* bs = Bs + cur * STAGE_F;
#pragma unroll
        for (int ks = 0; ks < 4; ks++) {
            const int k0 = ks * 8;
            uint32_t ua[2][4], ub[8][2];
#pragma unroll
            for (int mf = 0; mf < 2; mf++) {
                int r0 = wm * 32 + mf * 16 + g;
                ua[mf][0] = as[sw_off(r0,     k0 + c)];
                ua[mf][1] = as[sw_off(r0 + 8, k0 + c)];
                ua[mf][2] = as[sw_off(r0,     k0 + c + 4)];
                ua[mf][3] = as[sw_off(r0 + 8, k0 + c + 4)];
            }
#pragma unroll
            for (int nf = 0; nf < 8; nf++) {
                int n = wn * 64 + nf * 8 + g;
                ub[nf][0] = bs[sw_off(n, k0 + c)];
                ub[nf][1] = bs[sw_off(n, k0 + c + 4)];
            }
#pragma unroll
            for (int mf = 0; mf < 2; mf++)
#pragma unroll
                for (int nf = 0; nf < 8; nf++) mma_tf32(acc[mf][nf], ua[mf], ub[nf]);
        }
        __syncthreads();
    }

    if (EPI == 0) {
        // ---- fused epilogue: stage -> RoPE/round -> g_qkv ----
        const int which = n0 >> 11;          // 0=q, 1=k, 2=v
        const int hh = (n0 >> 7) & 15;
        float* stage = smem_all;             // 64 x PADW floats per pass

#pragma unroll
        for (int p = 0; p < 2; p++) {
            // write phase: warps with wm in {2p, 2p+1}
            if ((wm >> 1) == p) {
#pragma unroll
                for (int mf = 0; mf < 2; mf++) {
                    int rl = (wm & 1) * 32 + mf * 16 + g;   // row within pass
#pragma unroll
                    for (int nf = 0; nf < 8; nf++) {
                        int col = wn * 64 + nf * 8 + 2 * c;
                        *(float2*)(stage + rl * PADW + col) =
                            make_float2(acc[mf][nf].x, acc[mf][nf].y);
                        *(float2*)(stage + (rl + 8) * PADW + col) =
                            make_float2(acc[mf][nf].z, acc[mf][nf].w);
                    }
                }
            }
            __syncthreads();

            // read + rope + round + store: 256 threads, 64 rows, 4 threads/row
            {
                int rl = tid >> 2;             // 0..63
                int fg = tid & 3;
                int m = m0 + p * 64 + rl;
                int bb = m >> 11, t = m & 2047;
                float* dst = g_qkv +
                    ((((size_t)which * BB + bb) * HH + hh) * TT + t) * DD;
#pragma unroll
                for (int i = 0; i < 4; i++) {
                    int d = (fg + 4 * i) * 4;  // 0..60 step 4 (pair base)
                    float4 x1 = *(float4*)(stage + rl * PADW + d);
                    float4 x2 = *(float4*)(stage + rl * PADW + d + 64);
                    float4 o1, o2;
                    if (which < 2) {
                        float4 cs = *(const float4*)(g_cos + t * 64 + d);
                        float4 sn = *(const float4*)(g_sin + t * 64 + d);
                        o1.x = rtf(x1.x * cs.x - x2.x * sn.x);
                        o1.y = rtf(x1.y * cs.y - x2.y * sn.y);
                        o1.z = rtf(x1.z * cs.z - x2.z * sn.z);
                        o1.w = rtf(x1.w * cs.w - x2.w * sn.w);
                        o2.x = rtf(x2.x * cs.x + x1.x * sn.x);
                        o2.y = rtf(x2.y * cs.y + x1.y * sn.y);
                        o2.z = rtf(x2.z * cs.z + x1.z * sn.z);
                        o2.w = rtf(x2.w * cs.w + x1.w * sn.w);
                    } else {
                        o1.x = rtf(x1.x); o1.y = rtf(x1.y);
                        o1.z = rtf(x1.z); o1.w = rtf(x1.w);
                        o2.x = rtf(x2.x); o2.y = rtf(x2.y);
                        o2.z = rtf(x2.z); o2.w = rtf(x2.w);
                    }
                    *(float4*)(dst + d)      = o1;
                    *(float4*)(dst + d + 64) = o2;
                }
            }
            __syncthreads();
        }
    } else {
#pragma unroll
        for (int mf = 0; mf < 2; mf++) {
            int r0 = m0 + wm * 32 + mf * 16 + g;
            int r1 = r0 + 8;
#pragma unroll
            for (int nf = 0; nf < 8; nf++) {
                int col = n0 + wn * 64 + nf * 8 + 2 * c;
                *(float2*)(out + (size_t)r0 * N + col) = make_float2(acc[mf][nf].x, acc[mf][nf].y);
                *(float2*)(out + (size_t)r1 * N + col) = make_float2(acc[mf][nf].z, acc[mf][nf].w);
            }
        }
    }
}

// ---------------------------------------------------------------------------
// Flash attention (R12 structure; horizon margin 40 -> 24).
// ---------------------------------------------------------------------------
#define AM 128
#define AN 64
#define QST 132
#define KST 132
#define VST 136
#define PST 68

#define OFF_Q   0
#define OFF_KHI (AM * QST)
#define OFF_VHI (OFF_KHI + 2 * AN * KST)
#define OFF_P   (OFF_VHI + AN * VST)
#define ATTN_F  (OFF_P + AM * PST)
#define ATTN_SMEM (ATTN_F * 4)   // 204800 B

__global__ void __launch_bounds__(256, 1) attn_mma_kernel() {
    extern __shared__ float sm[];
    float* Qs = sm + OFF_Q;
    float* Khi[2] = { sm + OFF_KHI, sm + OFF_KHI + AN * KST };
    float* Vhi = sm + OFF_VHI;
    float* Ps  = sm + OFF_P;
    const uint32_t* uQs  = (const uint32_t*)Qs;
    const uint32_t* uVhi = (const uint32_t*)Vhi;
    const uint32_t* uPs  = (const uint32_t*)Ps;

    const int bh = blockIdx.y;
    const int b = bh >> 4;
    const int h = bh & 15;
    const int qt = (gridDim.x - 1) - blockIdx.x;
    const int i0 = qt * AM;
    const float slope = (float)exp2(-0.5 * (double)(h + 1));
    const float scale = 0.08838834764831843f;

    const float* Qg = g_qkv + (size_t)bh * TT * DD;
    const float* Kg = g_qkv + ((size_t)(BB * HH) + bh) * TT * DD;
    const float* Vg = g_qkv + ((size_t)(2 * BB * HH) + bh) * TT * DD;

    const int tid = threadIdx.x;
    const int w = tid >> 5, lane = tid & 31;
    const int g = lane >> 2, c = lane & 3;
    const int r0 = w * 16;

    const int ntiles = 2 * (qt + 1);

    for (int v = tid; v < AM * 32; v += 256) {
        int r = v >> 5, c4 = (v & 31) << 2;
        cp_async16(Qs + r * QST + c4, Qg + (size_t)(i0 + r) * DD + c4);
    }
    {
        const int j0 = (ntiles - 1) * AN;
        for (int v = tid; v < AN * 32; v += 256) {
            int r = v >> 5, c4 = (v & 31) << 2;
            cp_async16(Khi[0] + r * KST + c4, Kg + (size_t)(j0 + r) * DD + c4);
        }
    }
    asm volatile("cp.async.commit_group;\n");

    float4 o[16];
#pragma unroll
    for (int i = 0; i < 16; i++) o[i] = make_float4(0.f, 0.f, 0.f, 0.f);
    float mr0 = -INFINITY, mr1 = -INFINITY, lr0 = 0.f, lr1 = 0.f;

    for (int it = 0; it < ntiles; it++) {
        const int kt2 = ntiles - 1 - it;
        const int j0 = kt2 * AN;
        const int cur = it & 1, nxt = cur ^ 1;

        const bool last = (kt2 == 0) ||
            (slope * (float)(i0 - (kt2 - 1) * AN - 63) > 24.0f);

        __syncthreads();

        for (int v = tid; v < AN * 32; v += 256) {
            int r = v >> 5, c4 = (v & 31) << 2;
            cp_async16(Vhi + r * VST + c4, Vg + (size_t)(j0 + r) * DD + c4);
        }
        asm volatile("cp.async.commit_group;\n");

        if (!last) {
            const int jn = (kt2 - 1) * AN;
            for (int v = tid; v < AN * 32; v += 256) {
                int r = v >> 5, c4 = (v & 31) << 2;
                cp_async16(Khi[nxt] + r * KST + c4, Kg + (size_t)(jn + r) * DD + c4);
            }
        }
        asm volatile("cp.async.commit_group;\n");

        asm volatile("cp.async.wait_group 2;\n");
        __syncthreads();

        const uint32_t* uKhi = (const uint32_t*)Khi[cur];
        float4 s[8];
#pragma unroll
        for (int nf = 0; nf < 8; nf++) s[nf] = make_float4(0.f, 0.f, 0.f, 0.f);
#pragma unroll 4
        for (int kc = 0; kc < 16; kc++) {
            const int k0 = kc * 8;
            uint32_t ua[4];
            ua[0] = uQs[(r0 + g)     * QST + k0 + c];
            ua[1] = uQs[(r0 + g + 8) * QST + k0 + c];
            ua[2] = uQs[(r0 + g)     * QST + k0 + c + 4];
            ua[3] = uQs[(r0 + g + 8) * QST + k0 + c + 4];
#pragma unroll
            for (int nf = 0; nf < 8; nf++) {
                uint32_t bhi[2];
                int nb = (nf * 8 + g) * KST + k0;
                bhi[0] = uKhi[nb + c]; bhi[1] = uKhi[nb + c + 4];
                mma_tf32(s[nf], ua, bhi);
            }
        }

        const int ig0 = i0 + r0 + g;
        const int ig1 = ig0 + 8;
        const bool needmask = (kt2 >= ntiles - 2);
        float tm0 = -INFINITY, tm1 = -INFINITY;
#pragma unroll
        for (int nf = 0; nf < 8; nf++) {
            int jb = j0 + nf * 8 + 2 * c;
            if (needmask) {
                s[nf].x = (jb     <= ig0) ? fmaf(slope, (float)(jb     - ig0), s[nf].x * scale) : NEGF;
                s[nf].y = (jb + 1 <= ig0) ? fmaf(slope, (float)(jb + 1 - ig0), s[nf].y * scale) : NEGF;
                s[nf].z = (jb     <= ig1) ? fmaf(slope, (float)(jb     - ig1), s[nf].z * scale) : NEGF;
                s[nf].w = (jb + 1 <= ig1) ? fmaf(slope, (float)(jb + 1 - ig1), s[nf].w * scale) : NEGF;
            } else {
                s[nf].x = fmaf(slope, (float)(jb     - ig0), s[nf].x * scale);
                s[nf].y = fmaf(slope, (float)(jb + 1 - ig0), s[nf].y * scale);
                s[nf].z = fmaf(slope, (float)(jb     - ig1), s[nf].z * scale);
                s[nf].w = fmaf(slope, (float)(jb + 1 - ig1), s[nf].w * scale);
            }
            tm0 = fmaxf(tm0, fmaxf(s[nf].x, s[nf].y));
            tm1 = fmaxf(tm1, fmaxf(s[nf].z, s[nf].w));
        }
        tm0 = fmaxf(tm0, __shfl_xor_sync(0xffffffffu, tm0, 1));
        tm0 = fmaxf(tm0, __shfl_xor_sync(0xffffffffu, tm0, 2));
        tm1 = fmaxf(tm1, __shfl_xor_sync(0xffffffffu, tm1, 1));
        tm1 = fmaxf(tm1, __shfl_xor_sync(0xffffffffu, tm1, 2));

        float mn0 = fmaxf(mr0, tm0), mn1 = fmaxf(mr1, tm1);
        float corr0 = __expf(mr0 - mn0), corr1 = __expf(mr1 - mn1);
        mr0 = mn0; mr1 = mn1;

        float rs0 = 0.f, rs1 = 0.f;
#pragma unroll
        for (int nf = 0; nf < 8; nf++) {
            float p0 = rtf(__expf(s[nf].x - mn0));
            float p1 = rtf(__expf(s[nf].y - mn0));
            float p2 = rtf(__expf(s[nf].z - mn1));
            float p3 = rtf(__expf(s[nf].w - mn1));
            rs0 += p0 + p1;
            rs1 += p2 + p3;
            *(float2*)(Ps + (r0 + g)     * PST + nf * 8 + 2 * c) = make_float2(p0, p1);
            *(float2*)(Ps + (r0 + g + 8) * PST + nf * 8 + 2 * c) = make_float2(p2, p3);
        }
        rs0 += __shfl_xor_sync(0xffffffffu, rs0, 1);
        rs0 += __shfl_xor_sync(0xffffffffu, rs0, 2);
        rs1 += __shfl_xor_sync(0xffffffffu, rs1, 1);
        rs1 += __shfl_xor_sync(0xffffffffu, rs1, 2);
        lr0 = lr0 * corr0 + rs0;
        lr1 = lr1 * corr1 + rs1;

        bool noresc = __all_sync(0xffffffffu, (corr0 == 1.0f) && (corr1 == 1.0f));
        if (!noresc) {
#pragma unroll
            for (int nf = 0; nf < 16; nf++) {
                o[nf].x *= corr0; o[nf].y *= corr0;
                o[nf].z *= corr1; o[nf].w *= corr1;
            }
        }

        asm volatile("cp.async.wait_group 1;\n");
        __syncthreads();

#pragma unroll 2
        for (int kc = 0; kc < 8; kc++) {
            const int k0 = kc * 8;
            uint32_t ua[4];
            ua[0] = uPs[(r0 + g)     * PST + k0 + c];
            ua[1] = uPs[(r0 + g + 8) * PST + k0 + c];
            ua[2] = uPs[(r0 + g)     * PST + k0 + c + 4];
            ua[3] = uPs[(r0 + g + 8) * PST + k0 + c + 4];
#pragma unroll
            for (int nf = 0; nf < 16; nf++) {
                uint32_t bhi[2];
                bhi[0] = uVhi[(k0 + c)     * VST + nf * 8 + g];
                bhi[1] = uVhi[(k0 + c + 4) * VST + nf * 8 + g];
                mma_tf32(o[nf], ua, bhi);
            }
        }

        if (last) break;
    }

    asm volatile("cp.async.wait_group 0;\n");

    float inv0 = 1.f / lr0, inv1 = 1.f / lr1;
    int t0 = i0 + r0 + g, t1 = t0 + 8;
    float* d0 = g_att + ((size_t)b * TT + t0) * CC + h * DD;
    float* d1 = g_att + ((size_t)b * TT + t1) * CC + h * DD;
#pragma unroll
    for (int nf = 0; nf < 16; nf++) {
        int col = nf * 8 + 2 * c;
        *(float2*)(d0 + col) = make_float2(rtf(o[nf].x * inv0), rtf(o[nf].y * inv0));
        *(float2*)(d1 + col) = make_float2(rtf(o[nf].z * inv1), rtf(o[nf].w * inv1));
    }
}

// ---------------------------------------------------------------------------
extern "C" void kernel_launch(void* const* d_in, const int* in_sizes, int n_in,
                              void* d_out, int out_size) {
    (void)in_sizes; (void)n_in; (void)out_size;
    const float* x    = (const float*)d_in[0];
    const float* Wqkv = (const float*)d_in[3];
    const float* Wout = (const float*)d_in[4];
    float* out = (float*)d_out;

    rope_table_kernel<<<TT / 4, 256>>>();

    {
        int n4x = BB * TT * CC / 4;
        int n4q = 3 * CC * CC / 4;
        int n4o = CC * CC / 4;
        cvt_tf32_kernel<0><<<(n4x + 255) / 256, 256>>>(x, n4x);
        cvt_tf32_kernel<1><<<(n4q + 255) / 256, 256>>>(Wqkv, n4q);
        cvt_tf32_kernel<2><<<(n4o + 255) / 256, 256>>>(Wout, n4o);
    }

    dim3 g1(3 * CC / 128, BB * TT / 128);   // (48, 32)
    gemm_tf32<0><<<g1, 256>>>(nullptr);     // fused RoPE epilogue

    cudaFuncSetAttribute(attn_mma_kernel,
                         cudaFuncAttributeMaxDynamicSharedMemorySize, ATTN_SMEM);
    dim3 g2(TT / AM, BB * HH);              // (16, 32)
    attn_mma_kernel<<<g2, 256, ATTN_SMEM>>>();

    dim3 g3(CC / 128, BB * TT / 128);       // (16, 32)
    gemm_tf32<1><<<g3, 256>>>(out);
}

// round 14
// speedup vs baseline: 1.1515x; 1.1515x over previous
#include <cuda_runtime.h>
#include <math.h>
#include <stdint.h>

#define BB 2
#define TT 2048
#define CC 2048
#define HH 16
#define DD 128
#define NEGF -1000000000.0f

// Scratch (device globals — referenced ONLY from device code)
__device__ float g_qkv[(size_t)3 * BB * HH * TT * DD];  // [3][B][H][T][D]
__device__ float g_att[(size_t)BB * TT * CC];           // [B][T][C] (tf32-rounded)
__device__ float g_xc[(size_t)BB * TT * CC];            // x rounded to tf32
__device__ float g_wqc[(size_t)3 * CC * CC];            // Wqkv rounded
__device__ float g_woc[(size_t)CC * CC];                // Wout rounded
__device__ float g_cos[TT * 64];
__device__ float g_sin[TT * 64];

// ---------------------------------------------------------------------------
__device__ __forceinline__ uint32_t f2tf32(float x) {
    uint32_t r;
    asm volatile("cvt.rna.tf32.f32 %0, %1;\n" : "=r"(r) : "f"(x));
    return r;
}
__device__ __forceinline__ float rtf(float x) { return __uint_as_float(f2tf32(x)); }
__device__ __forceinline__ void cp_async16(void* smem, const void* gmem) {
    uint32_t s = (uint32_t)__cvta_generic_to_shared(smem);
    asm volatile("cp.async.cg.shared.global [%0], [%1], 16;\n" :: "r"(s), "l"(gmem));
}
__device__ __forceinline__ void mma_tf32(float4& d, const uint32_t a[4], const uint32_t b[2]) {
    asm volatile(
        "mma.sync.aligned.m16n8k8.row.col.f32.tf32.tf32.f32 "
        "{%0,%1,%2,%3}, {%4,%5,%6,%7}, {%8,%9}, {%0,%1,%2,%3};\n"
        : "+f"(d.x), "+f"(d.y), "+f"(d.z), "+f"(d.w)
        : "r"(a[0]), "r"(a[1]), "r"(a[2]), "r"(a[3]), "r"(b[0]), "r"(b[1]));
}

// ---------------------------------------------------------------------------
__global__ void rope_table_kernel() {   // 256 threads, 4 positions/block
    int t = blockIdx.x * 4 + (threadIdx.x >> 6);
    int d = threadIdx.x & 63;
    double inv = exp2(-((double)(2 * d) / 128.0) * log2(10000.0));
    float f = (float)t * (float)inv;
    g_cos[t * 64 + d] = cosf(f);
    g_sin[t * 64 + d] = sinf(f);
}

// Single fused rounding pass: x -> g_xc, Wqkv -> g_wqc, Wout -> g_woc.
#define N4X (BB * TT * CC / 4)
#define N4Q (3 * CC * CC / 4)
#define N4O (CC * CC / 4)
__global__ void cvt_all_kernel(const float* __restrict__ x,
                               const float* __restrict__ wq,
                               const float* __restrict__ wo) {
    int i = blockIdx.x * blockDim.x + threadIdx.x;
    const float4* src;
    float* dst;
    int j;
    if (i < N4X)            { src = (const float4*)x;  dst = g_xc;  j = i; }
    else if (i < N4X + N4Q) { src = (const float4*)wq; dst = g_wqc; j = i - N4X; }
    else if (i < N4X + N4Q + N4O) { src = (const float4*)wo; dst = g_woc; j = i - N4X - N4Q; }
    else return;
    float4 v = src[j];
    v.x = rtf(v.x); v.y = rtf(v.y); v.z = rtf(v.z); v.w = rtf(v.w);
    ((float4*)dst)[j] = v;
}

// ---------------------------------------------------------------------------
// RoPE + rounding: q,k: rope + round to tf32; v: round. In place.
// 256 threads, 4 rows per block.
// ---------------------------------------------------------------------------
__global__ void rope_split_kernel() {
    int row = blockIdx.x * 4 + (threadIdx.x >> 6);
    int t = row & (TT - 1);
    int s = row >> 11;
    float* p = g_qkv + ((size_t)s * TT + t) * DD;
    int d = threadIdx.x & 63;

    if (s < 2 * BB * HH) {
        float cs = g_cos[t * 64 + d], sn = g_sin[t * 64 + d];
        float x1 = p[d], x2 = p[d + 64];
        p[d]      = rtf(x1 * cs - x2 * sn);
        p[d + 64] = rtf(x2 * cs + x1 * sn);
    } else {
        p[d]      = rtf(p[d]);
        p[d + 64] = rtf(p[d + 64]);
    }
}

// ---------------------------------------------------------------------------
// tf32 mma.sync GEMM (NT), 2-stage cp.async, static 64KB smem (R12-proven,
// untouched).
// ---------------------------------------------------------------------------
#define GBK 32
#define STAGE_F (128 * GBK)

__device__ __forceinline__ int sw_off(int row, int k) {
    return row * GBK + ((((k >> 2) ^ (row & 7)) << 2) | (k & 3));
}

template <int EPI>
__global__ void __launch_bounds__(256, 2) gemm_tf32(float* __restrict__ out) {
    __shared__ uint32_t As[2][STAGE_F];
    __shared__ uint32_t Bs[2][STAGE_F];

    const float* A = (EPI == 0) ? (const float*)g_xc  : (const float*)g_att;
    const float* W = (EPI == 0) ? (const float*)g_wqc : (const float*)g_woc;
    const int K = CC;
    const int N = (EPI == 0) ? 3 * CC : CC;

    const int tid = threadIdx.x;
    const int m0 = blockIdx.y * 128, n0 = blockIdx.x * 128;

    const int wid = tid >> 5;
    const int lane = tid & 31;
    const int wm = wid & 3;
    const int wn = wid >> 2;
    const int g = lane >> 2;
    const int c = lane & 3;

    const int lr = tid >> 3;
    const int lc4 = tid & 7;

    float4 acc[2][8];
#pragma unroll
    for (int i = 0; i < 2; i++)
#pragma unroll
        for (int j = 0; j < 8; j++) acc[i][j] = make_float4(0.f, 0.f, 0.f, 0.f);

    const int NT = K / GBK;

    {
#pragma unroll
        for (int i = 0; i < 4; i++) {
            int r = lr + i * 32;
            int sw = (lc4 ^ (r & 7)) << 2;
            cp_async16(&As[0][r * GBK + sw], A + (size_t)(m0 + r) * K + lc4 * 4);
            cp_async16(&Bs[0][r * GBK + sw], W + (size_t)(n0 + r) * K + lc4 * 4);
        }
        asm volatile("cp.async.commit_group;\n");
    }

    for (int kt = 0; kt < NT; kt++) {
        int cur = kt & 1;
        if (kt + 1 < NT) {
            int nxt = cur ^ 1;
            int k0 = (kt + 1) * GBK;
#pragma unroll
            for (int i = 0; i < 4; i++) {
                int r = lr + i * 32;
                int sw = (lc4 ^ (r & 7)) << 2;
                cp_async16(&As[nxt][r * GBK + sw], A + (size_t)(m0 + r) * K + k0 + lc4 * 4);
                cp_async16(&Bs[nxt][r * GBK + sw], W + (size_t)(n0 + r) * K + k0 + lc4 * 4);
            }
        }
        asm volatile("cp.async.commit_group;\n");
        asm volatile("cp.async.wait_group 1;\n");
        __syncthreads();

        const uint32_t* as = As[cur];
        const uint32_t* bs = Bs[cur];
#pragma unroll
        for (int ks = 0; ks < 4; ks++) {
            const int k0 = ks * 8;
            uint32_t ua[2][4], ub[8][2];
#pragma unroll
            for (int mf = 0; mf < 2; mf++) {
                int r0 = wm * 32 + mf * 16 + g;
                ua[mf][0] = as[sw_off(r0,     k0 + c)];
                ua[mf][1] = as[sw_off(r0 + 8, k0 + c)];
                ua[mf][2] = as[sw_off(r0,     k0 + c + 4)];
                ua[mf][3] = as[sw_off(r0 + 8, k0 + c + 4)];
            }
#pragma unroll
            for (int nf = 0; nf < 8; nf++) {
                int n = wn * 64 + nf * 8 + g;
                ub[nf][0] = bs[sw_off(n, k0 + c)];
                ub[nf][1] = bs[sw_off(n, k0 + c + 4)];
            }
#pragma unroll
            for (int mf = 0; mf < 2; mf++)
#pragma unroll
                for (int nf = 0; nf < 8; nf++) mma_tf32(acc[mf][nf], ua[mf], ub[nf]);
        }
        __syncthreads();
    }

    if (EPI == 0) {
        const int which = n0 >> 11;
        const int hh = (n0 >> 7) & 15;
#pragma unroll
        for (int mf = 0; mf < 2; mf++) {
            int r0 = m0 + wm * 32 + mf * 16 + g;
            int b0i = r0 >> 11, t0 = r0 & 2047;
            int r1 = r0 + 8;
            int b1i = r1 >> 11, t1 = r1 & 2047;
            float* base0 = g_qkv + ((((size_t)which * BB + b0i) * HH + hh) * TT + t0) * DD;
            float* base1 = g_qkv + ((((size_t)which * BB + b1i) * HH + hh) * TT + t1) * DD;
#pragma unroll
            for (int nf = 0; nf < 8; nf++) {
                int col = wn * 64 + nf * 8 + 2 * c;
                *(float2*)(base0 + col) = make_float2(acc[mf][nf].x, acc[mf][nf].y);
                *(float2*)(base1 + col) = make_float2(acc[mf][nf].z, acc[mf][nf].w);
            }
        }
    } else {
#pragma unroll
        for (int mf = 0; mf < 2; mf++) {
            int r0 = m0 + wm * 32 + mf * 16 + g;
            int r1 = r0 + 8;
#pragma unroll
            for (int nf = 0; nf < 8; nf++) {
                int col = n0 + wn * 64 + nf * 8 + 2 * c;
                *(float2*)(out + (size_t)r0 * N + col) = make_float2(acc[mf][nf].x, acc[mf][nf].y);
                *(float2*)(out + (size_t)r1 * N + col) = make_float2(acc[mf][nf].z, acc[mf][nf].w);
            }
        }
    }
}

// ---------------------------------------------------------------------------
// Flash attention (R12 structure; horizon margin 24, validated in R13).
// Key-tiles descending from diagonal; ALiBi horizon break; causal mask only
// on the two diagonal tiles; warp-uniform rescale skip.
// K hi-only (1-pass S), Khi double-buffered, V single-buffered split waits.
// P rounded rna at store; PV single pass.
// ---------------------------------------------------------------------------
#define AM 128
#define AN 64
#define QST 132
#define KST 132
#define VST 136
#define PST 68

#define OFF_Q   0
#define OFF_KHI (AM * QST)
#define OFF_VHI (OFF_KHI + 2 * AN * KST)
#define OFF_P   (OFF_VHI + AN * VST)
#define ATTN_F  (OFF_P + AM * PST)
#define ATTN_SMEM (ATTN_F * 4)   // 204800 B

__global__ void __launch_bounds__(256, 1) attn_mma_kernel() {
    extern __shared__ float sm[];
    float* Qs = sm + OFF_Q;
    float* Khi[2] = { sm + OFF_KHI, sm + OFF_KHI + AN * KST };
    float* Vhi = sm + OFF_VHI;
    float* Ps  = sm + OFF_P;
    const uint32_t* uQs  = (const uint32_t*)Qs;
    const uint32_t* uVhi = (const uint32_t*)Vhi;
    const uint32_t* uPs  = (const uint32_t*)Ps;

    const int bh = blockIdx.y;
    const int b = bh >> 4;
    const int h = bh & 15;
    const int qt = (gridDim.x - 1) - blockIdx.x;   // heavy tiles first
    const int i0 = qt * AM;
    const float slope = (float)exp2(-0.5 * (double)(h + 1));
    const float scale = 0.08838834764831843f;      // 1/sqrt(128)

    const float* Qg = g_qkv + (size_t)bh * TT * DD;
    const float* Kg = g_qkv + ((size_t)(BB * HH) + bh) * TT * DD;
    const float* Vg = g_qkv + ((size_t)(2 * BB * HH) + bh) * TT * DD;

    const int tid = threadIdx.x;
    const int w = tid >> 5, lane = tid & 31;
    const int g = lane >> 2, c = lane & 3;
    const int r0 = w * 16;

    const int ntiles = 2 * (qt + 1);

    // prologue group: Q tile + K(ntiles-1)  (start at the diagonal)
    for (int v = tid; v < AM * 32; v += 256) {
        int r = v >> 5, c4 = (v & 31) << 2;
        cp_async16(Qs + r * QST + c4, Qg + (size_t)(i0 + r) * DD + c4);
    }
    {
        const int j0 = (ntiles - 1) * AN;
        for (int v = tid; v < AN * 32; v += 256) {
            int r = v >> 5, c4 = (v & 31) << 2;
            cp_async16(Khi[0] + r * KST + c4, Kg + (size_t)(j0 + r) * DD + c4);
        }
    }
    asm volatile("cp.async.commit_group;\n");

    float4 o[16];
#pragma unroll
    for (int i = 0; i < 16; i++) o[i] = make_float4(0.f, 0.f, 0.f, 0.f);
    float mr0 = -INFINITY, mr1 = -INFINITY, lr0 = 0.f, lr1 = 0.f;

    for (int it = 0; it < ntiles; it++) {
        const int kt2 = ntiles - 1 - it;       // descending from diagonal
        const int j0 = kt2 * AN;
        const int cur = it & 1, nxt = cur ^ 1;

        const bool last = (kt2 == 0) ||
            (slope * (float)(i0 - (kt2 - 1) * AN - 63) > 24.0f);

        __syncthreads();  // PV(prev) done (V free); S(prev) done (K[nxt] free)

        // issue V(kt2)  [group]
        for (int v = tid; v < AN * 32; v += 256) {
            int r = v >> 5, c4 = (v & 31) << 2;
            cp_async16(Vhi + r * VST + c4, Vg + (size_t)(j0 + r) * DD + c4);
        }
        asm volatile("cp.async.commit_group;\n");

        // issue K(kt2-1) prefetch into nxt  [group]
        if (!last) {
            const int jn = (kt2 - 1) * AN;
            for (int v = tid; v < AN * 32; v += 256) {
                int r = v >> 5, c4 = (v & 31) << 2;
                cp_async16(Khi[nxt] + r * KST + c4, Kg + (size_t)(jn + r) * DD + c4);
            }
        }
        asm volatile("cp.async.commit_group;\n");

        // K(kt2) (oldest pending) ready
        asm volatile("cp.async.wait_group 2;\n");
        __syncthreads();

        // ---- S = Qhi * Khi (single pass), 16 x 64 per warp ----
        const uint32_t* uKhi = (const uint32_t*)Khi[cur];
        float4 s[8];
#pragma unroll
        for (int nf = 0; nf < 8; nf++) s[nf] = make_float4(0.f, 0.f, 0.f, 0.f);
#pragma unroll 4
        for (int kc = 0; kc < 16; kc++) {
            const int k0 = kc * 8;
            uint32_t ua[4];
            ua[0] = uQs[(r0 + g)     * QST + k0 + c];
            ua[1] = uQs[(r0 + g + 8) * QST + k0 + c];
            ua[2] = uQs[(r0 + g)     * QST + k0 + c + 4];
            ua[3] = uQs[(r0 + g + 8) * QST + k0 + c + 4];
#pragma unroll
            for (int nf = 0; nf < 8; nf++) {
                uint32_t bhi[2];
                int nb = (nf * 8 + g) * KST + k0;
                bhi[0] = uKhi[nb + c]; bhi[1] = uKhi[nb + c + 4];
                mma_tf32(s[nf], ua, bhi);
            }
        }

        // ---- scale + ALiBi (+causal mask only on diagonal tiles) ----
        const int ig0 = i0 + r0 + g;
        const int ig1 = ig0 + 8;
        const bool needmask = (kt2 >= ntiles - 2);
        float tm0 = -INFINITY, tm1 = -INFINITY;
#pragma unroll
        for (int nf = 0; nf < 8; nf++) {
            int jb = j0 + nf * 8 + 2 * c;
            if (needmask) {
                s[nf].x = (jb     <= ig0) ? fmaf(slope, (float)(jb     - ig0), s[nf].x * scale) : NEGF;
                s[nf].y = (jb + 1 <= ig0) ? fmaf(slope, (float)(jb + 1 - ig0), s[nf].y * scale) : NEGF;
                s[nf].z = (jb     <= ig1) ? fmaf(slope, (float)(jb     - ig1), s[nf].z * scale) : NEGF;
                s[nf].w = (jb + 1 <= ig1) ? fmaf(slope, (float)(jb + 1 - ig1), s[nf].w * scale) : NEGF;
            } else {
                s[nf].x = fmaf(slope, (float)(jb     - ig0), s[nf].x * scale);
                s[nf].y = fmaf(slope, (float)(jb + 1 - ig0), s[nf].y * scale);
                s[nf].z = fmaf(slope, (float)(jb     - ig1), s[nf].z * scale);
                s[nf].w = fmaf(slope, (float)(jb + 1 - ig1), s[nf].w * scale);
            }
            tm0 = fmaxf(tm0, fmaxf(s[nf].x, s[nf].y));
            tm1 = fmaxf(tm1, fmaxf(s[nf].z, s[nf].w));
        }
        tm0 = fmaxf(tm0, __shfl_xor_sync(0xffffffffu, tm0, 1));
        tm0 = fmaxf(tm0, __shfl_xor_sync(0xffffffffu, tm0, 2));
        tm1 = fmaxf(tm1, __shfl_xor_sync(0xffffffffu, tm1, 1));
        tm1 = fmaxf(tm1, __shfl_xor_sync(0xffffffffu, tm1, 2));

        float mn0 = fmaxf(mr0, tm0), mn1 = fmaxf(mr1, tm1);
        float corr0 = __expf(mr0 - mn0), corr1 = __expf(mr1 - mn1);
        mr0 = mn0; mr1 = mn1;

        float rs0 = 0.f, rs1 = 0.f;
#pragma unroll
        for (int nf = 0; nf < 8; nf++) {
            float p0 = rtf(__expf(s[nf].x - mn0));
            float p1 = rtf(__expf(s[nf].y - mn0));
            float p2 = rtf(__expf(s[nf].z - mn1));
            float p3 = rtf(__expf(s[nf].w - mn1));
            rs0 += p0 + p1;
            rs1 += p2 + p3;
            *(float2*)(Ps + (r0 + g)     * PST + nf * 8 + 2 * c) = make_float2(p0, p1);
            *(float2*)(Ps + (r0 + g + 8) * PST + nf * 8 + 2 * c) = make_float2(p2, p3);
        }
        rs0 += __shfl_xor_sync(0xffffffffu, rs0, 1);
        rs0 += __shfl_xor_sync(0xffffffffu, rs0, 2);
        rs1 += __shfl_xor_sync(0xffffffffu, rs1, 1);
        rs1 += __shfl_xor_sync(0xffffffffu, rs1, 2);
        lr0 = lr0 * corr0 + rs0;
        lr1 = lr1 * corr1 + rs1;

        bool noresc = __all_sync(0xffffffffu, (corr0 == 1.0f) && (corr1 == 1.0f));
        if (!noresc) {
#pragma unroll
            for (int nf = 0; nf < 16; nf++) {
                o[nf].x *= corr0; o[nf].y *= corr0;
                o[nf].z *= corr1; o[nf].w *= corr1;
            }
        }

        // V(kt2) ready (only K prefetch may remain pending)
        asm volatile("cp.async.wait_group 1;\n");
        __syncthreads();

        // ---- O += P * Vhi (single pass), 16 x 128 per warp ----
#pragma unroll 2
        for (int kc = 0; kc < 8; kc++) {
            const int k0 = kc * 8;
            uint32_t ua[4];
            ua[0] = uPs[(r0 + g)     * PST + k0 + c];
            ua[1] = uPs[(r0 + g + 8) * PST + k0 + c];
            ua[2] = uPs[(r0 + g)     * PST + k0 + c + 4];
            ua[3] = uPs[(r0 + g + 8) * PST + k0 + c + 4];
#pragma unroll
            for (int nf = 0; nf < 16; nf++) {
                uint32_t bhi[2];
                bhi[0] = uVhi[(k0 + c)     * VST + nf * 8 + g];
                bhi[1] = uVhi[(k0 + c + 4) * VST + nf * 8 + g];
                mma_tf32(o[nf], ua, bhi);
            }
        }

        if (last) break;   // remaining tiles beyond the ALiBi horizon
    }

    asm volatile("cp.async.wait_group 0;\n");  // drain pending groups

    // ---- epilogue ----
    float inv0 = 1.f / lr0, inv1 = 1.f / lr1;
    int t0 = i0 + r0 + g, t1 = t0 + 8;
    float* d0 = g_att + ((size_t)b * TT + t0) * CC + h * DD;
    float* d1 = g_att + ((size_t)b * TT + t1) * CC + h * DD;
#pragma unroll
    for (int nf = 0; nf < 16; nf++) {
        int col = nf * 8 + 2 * c;
        *(float2*)(d0 + col) = make_float2(rtf(o[nf].x * inv0), rtf(o[nf].y * inv0));
        *(float2*)(d1 + col) = make_float2(rtf(o[nf].z * inv1), rtf(o[nf].w * inv1));
    }
}

// ---------------------------------------------------------------------------
extern "C" void kernel_launch(void* const* d_in, const int* in_sizes, int n_in,
                              void* d_out, int out_size) {
    (void)in_sizes; (void)n_in; (void)out_size;
    const float* x    = (const float*)d_in[0];
    const float* Wqkv = (const float*)d_in[3];
    const float* Wout = (const float*)d_in[4];
    float* out = (float*)d_out;

    rope_table_kernel<<<TT / 4, 256>>>();

    {
        int n4 = N4X + N4Q + N4O;
        cvt_all_kernel<<<(n4 + 255) / 256, 256>>>(x, Wqkv, Wout);
    }

    dim3 g1(3 * CC / 128, BB * TT / 128);   // (48, 32)
    gemm_tf32<0><<<g1, 256>>>(nullptr);

    rope_split_kernel<<<3 * BB * HH * TT / 4, 256>>>();

    cudaFuncSetAttribute(attn_mma_kernel,
                         cudaFuncAttributeMaxDynamicSharedMemorySize, ATTN_SMEM);
    dim3 g2(TT / AM, BB * HH);              // (16, 32)
    attn_mma_kernel<<<g2, 256, ATTN_SMEM>>>();

    dim3 g3(CC / 128, BB * TT / 128);       // (16, 32)
    gemm_tf32<1><<<g3, 256>>>(out);
}

// round 16
// speedup vs baseline: 1.2784x; 1.1102x over previous
#include <cuda_runtime.h>
#include <math.h>
#include <stdint.h>

#define BB 2
#define TT 2048
#define CC 2048
#define HH 16
#define DD 128
#define NEGF -1000000000.0f

// Scratch (device globals — referenced ONLY from device code)
// g_xc/g_wqc/g_woc/g_att are stored K-PERMUTED: within each 16-aligned block
// of the K (=C) dimension, element with original offset o lives at address
// (o&3)*4 + (o>>2). Both GEMM operands share the K dim, so the permutation
// cancels in the dot product (pure reordering of the summation layout).
__device__ float g_qkv[(size_t)3 * BB * HH * TT * DD];  // [3][B][H][T][D]
__device__ float g_att[(size_t)BB * TT * CC];           // [B][T][C] tf32, K-perm
__device__ float g_xc[(size_t)BB * TT * CC];            // x tf32, K-perm
__device__ float g_wqc[(size_t)3 * CC * CC];            // Wqkv tf32, K-perm
__device__ float g_woc[(size_t)CC * CC];                // Wout tf32, K-perm
__device__ float g_cos[TT * 64];
__device__ float g_sin[TT * 64];

// ---------------------------------------------------------------------------
__device__ __forceinline__ uint32_t f2tf32(float x) {
    uint32_t r;
    asm volatile("cvt.rna.tf32.f32 %0, %1;\n" : "=r"(r) : "f"(x));
    return r;
}
__device__ __forceinline__ float rtf(float x) { return __uint_as_float(f2tf32(x)); }
__device__ __forceinline__ void cp_async16(void* smem, const void* gmem) {
    uint32_t s = (uint32_t)__cvta_generic_to_shared(smem);
    asm volatile("cp.async.cg.shared.global [%0], [%1], 16;\n" :: "r"(s), "l"(gmem));
}
__device__ __forceinline__ void mma_tf32(float4& d, const uint32_t a[4], const uint32_t b[2]) {
    asm volatile(
        "mma.sync.aligned.m16n8k8.row.col.f32.tf32.tf32.f32 "
        "{%0,%1,%2,%3}, {%4,%5,%6,%7}, {%8,%9}, {%0,%1,%2,%3};\n"
        : "+f"(d.x), "+f"(d.y), "+f"(d.z), "+f"(d.w)
        : "r"(a[0]), "r"(a[1]), "r"(a[2]), "r"(a[3]), "r"(b[0]), "r"(b[1]));
}

// ---------------------------------------------------------------------------
__global__ void rope_table_kernel() {   // 256 threads, 4 positions/block
    int t = blockIdx.x * 4 + (threadIdx.x >> 6);
    int d = threadIdx.x & 63;
    double inv = exp2(-((double)(2 * d) / 128.0) * log2(10000.0));
    float f = (float)t * (float)inv;
    g_cos[t * 64 + d] = cosf(f);
    g_sin[t * 64 + d] = sinf(f);
}

// Fused rounding + K-permute pass. Each thread handles one 16-float block:
// out[a*4+j'] layout: address group a holds originals {a, a+4, a+8, a+12}.
#define NX16 (BB * TT * CC / 16)
#define NQ16 (3 * CC * CC / 16)
#define NO16 (CC * CC / 16)
__global__ void cvt_perm_kernel(const float* __restrict__ x,
                                const float* __restrict__ wq,
                                const float* __restrict__ wo) {
    int i = blockIdx.x * blockDim.x + threadIdx.x;
    const float* src; float* dst; int j;
    if (i < NX16)               { src = x;  dst = g_xc;  j = i; }
    else if (i < NX16 + NQ16)   { src = wq; dst = g_wqc; j = i - NX16; }
    else if (i < NX16 + NQ16 + NO16) { src = wo; dst = g_woc; j = i - NX16 - NQ16; }
    else return;
    const float4* s4 = (const float4*)(src + (size_t)j * 16);
    float4 i0 = s4[0], i1 = s4[1], i2 = s4[2], i3 = s4[3];
    float4* d4 = (float4*)(dst + (size_t)j * 16);
    d4[0] = make_float4(rtf(i0.x), rtf(i1.x), rtf(i2.x), rtf(i3.x));
    d4[1] = make_float4(rtf(i0.y), rtf(i1.y), rtf(i2.y), rtf(i3.y));
    d4[2] = make_float4(rtf(i0.z), rtf(i1.z), rtf(i2.z), rtf(i3.z));
    d4[3] = make_float4(rtf(i0.w), rtf(i1.w), rtf(i2.w), rtf(i3.w));
}

// ---------------------------------------------------------------------------
// RoPE + rounding: q,k: rope + round to tf32; v: round. In place (g_qkv is
// NOT permuted — attention reads it directly).
// ---------------------------------------------------------------------------
__global__ void rope_split_kernel() {
    int row = blockIdx.x * 4 + (threadIdx.x >> 6);
    int t = row & (TT - 1);
    int s = row >> 11;
    float* p = g_qkv + ((size_t)s * TT + t) * DD;
    int d = threadIdx.x & 63;

    if (s < 2 * BB * HH) {
        float cs = g_cos[t * 64 + d], sn = g_sin[t * 64 + d];
        float x1 = p[d], x2 = p[d + 64];
        p[d]      = rtf(x1 * cs - x2 * sn);
        p[d + 64] = rtf(x2 * cs + x1 * sn);
    } else {
        p[d]      = rtf(p[d]);
        p[d + 64] = rtf(p[d + 64]);
    }
}

// ---------------------------------------------------------------------------
// tf32 mma.sync GEMM (NT), 2-stage cp.async, K-permuted operands.
// Fragment loads are LDS.128 (one per thread per ks-pair per row/col) thanks
// to the gmem K-permutation. Smem swizzle: half-swap on row parity
// (chunk ^= (row&1)<<2) — conflict-free for loads and stores.
// Accumulation order per element identical to R14 (bit-exact).
// ---------------------------------------------------------------------------
#define GBK 32
#define STAGE_F (128 * GBK)

template <int EPI>
__global__ void __launch_bounds__(256, 2) gemm_tf32(float* __restrict__ out) {
    __shared__ uint32_t As[2][STAGE_F];
    __shared__ uint32_t Bs[2][STAGE_F];

    const float* A = (EPI == 0) ? (const float*)g_xc  : (const float*)g_att;
    const float* W = (EPI == 0) ? (const float*)g_wqc : (const float*)g_woc;
    const int K = CC;
    const int N = (EPI == 0) ? 3 * CC : CC;

    const int tid = threadIdx.x;
    const int m0 = blockIdx.y * 128, n0 = blockIdx.x * 128;

    const int wid = tid >> 5;
    const int lane = tid & 31;
    const int wm = wid & 3;
    const int wn = wid >> 2;
    const int g = lane >> 2;
    const int c = lane & 3;
    const int psw = (g & 1) << 2;          // fragment-row parity swizzle

    const int lr = tid >> 3;
    const int lc4 = tid & 7;

    float4 acc[2][8];
#pragma unroll
    for (int i = 0; i < 2; i++)
#pragma unroll
        for (int j = 0; j < 8; j++) acc[i][j] = make_float4(0.f, 0.f, 0.f, 0.f);

    const int NT = K / GBK;

    {
#pragma unroll
        for (int i = 0; i < 4; i++) {
            int r = lr + i * 32;
            int sw = (lc4 ^ ((r & 1) << 2)) << 2;
            cp_async16(&As[0][r * GBK + sw], A + (size_t)(m0 + r) * K + lc4 * 4);
            cp_async16(&Bs[0][r * GBK + sw], W + (size_t)(n0 + r) * K + lc4 * 4);
        }
        asm volatile("cp.async.commit_group;\n");
    }

    for (int kt = 0; kt < NT; kt++) {
        int cur = kt & 1;
        if (kt + 1 < NT) {
            int nxt = cur ^ 1;
            int k0 = (kt + 1) * GBK;
#pragma unroll
            for (int i = 0; i < 4; i++) {
                int r = lr + i * 32;
                int sw = (lc4 ^ ((r & 1) << 2)) << 2;
                cp_async16(&As[nxt][r * GBK + sw], A + (size_t)(m0 + r) * K + k0 + lc4 * 4);
                cp_async16(&Bs[nxt][r * GBK + sw], W + (size_t)(n0 + r) * K + k0 + lc4 * 4);
            }
        }
        asm volatile("cp.async.commit_group;\n");
        asm volatile("cp.async.wait_group 1;\n");
        __syncthreads();

        const uint32_t* as = As[cur];
        const uint32_t* bs = Bs[cur];
#pragma unroll
        for (int p = 0; p < 2; p++) {
            const int ch = ((p * 4 + c) ^ psw) * 4;
            uint4 qa[2][2];
#pragma unroll
            for (int mf = 0; mf < 2; mf++) {
                int ra = wm * 32 + mf * 16 + g;
                qa[mf][0] = *(const uint4*)(as + ra * GBK + ch);
                qa[mf][1] = *(const uint4*)(as + (ra + 8) * GBK + ch);
            }
#pragma unroll
            for (int nf = 0; nf < 8; nf++) {
                int n = wn * 64 + nf * 8 + g;
                uint4 rb = *(const uint4*)(bs + n * GBK + ch);
                uint32_t b0[2] = { rb.x, rb.y };
                uint32_t b1[2] = { rb.z, rb.w };
#pragma unroll
                for (int mf = 0; mf < 2; mf++) {
                    uint32_t a0[4] = { qa[mf][0].x, qa[mf][1].x, qa[mf][0].y, qa[mf][1].y };
                    mma_tf32(acc[mf][nf], a0, b0);
                    uint32_t a1[4] = { qa[mf][0].z, qa[mf][1].z, qa[mf][0].w, qa[mf][1].w };
                    mma_tf32(acc[mf][nf], a1, b1);
                }
            }
        }
        __syncthreads();
    }

    if (EPI == 0) {
        const int which = n0 >> 11;
        const int hh = (n0 >> 7) & 15;
#pragma unroll
        for (int mf = 0; mf < 2; mf++) {
            int r0 = m0 + wm * 32 + mf * 16 + g;
            int b0i = r0 >> 11, t0 = r0 & 2047;
            int r1 = r0 + 8;
            int b1i = r1 >> 11, t1 = r1 & 2047;
            float* base0 = g_qkv + ((((size_t)which * BB + b0i) * HH + hh) * TT + t0) * DD;
            float* base1 = g_qkv + ((((size_t)which * BB + b1i) * HH + hh) * TT + t1) * DD;
#pragma unroll
            for (int nf = 0; nf < 8; nf++) {
                int col = wn * 64 + nf * 8 + 2 * c;
                *(float2*)(base0 + col) = make_float2(acc[mf][nf].x, acc[mf][nf].y);
                *(float2*)(base1 + col) = make_float2(acc[mf][nf].z, acc[mf][nf].w);
            }
        }
    } else {
#pragma unroll
        for (int mf = 0; mf < 2; mf++) {
            int r0 = m0 + wm * 32 + mf * 16 + g;
            int r1 = r0 + 8;
#pragma unroll
            for (int nf = 0; nf < 8; nf++) {
                int col = n0 + wn * 64 + nf * 8 + 2 * c;
                *(float2*)(out + (size_t)r0 * N + col) = make_float2(acc[mf][nf].x, acc[mf][nf].y);
                *(float2*)(out + (size_t)r1 * N + col) = make_float2(acc[mf][nf].z, acc[mf][nf].w);
            }
        }
    }
}

// ---------------------------------------------------------------------------
// Flash attention (R14 champion structure; only the g_att epilogue addresses
// change: stores go to the K-permuted layout for the out-proj GEMM).
// ---------------------------------------------------------------------------
#define AM 128
#define AN 64
#define QST 132
#define KST 132
#define VST 136
#define PST 68

#define OFF_Q   0
#define OFF_KHI (AM * QST)
#define OFF_VHI (OFF_KHI + 2 * AN * KST)
#define OFF_P   (OFF_VHI + AN * VST)
#define ATTN_F  (OFF_P + AM * PST)
#define ATTN_SMEM (ATTN_F * 4)   // 204800 B

__global__ void __launch_bounds__(256, 1) attn_mma_kernel() {
    extern __shared__ float sm[];
    float* Qs = sm + OFF_Q;
    float* Khi[2] = { sm + OFF_KHI, sm + OFF_KHI + AN * KST };
    float* Vhi = sm + OFF_VHI;
    float* Ps  = sm + OFF_P;
    const uint32_t* uQs  = (const uint32_t*)Qs;
    const uint32_t* uVhi = (const uint32_t*)Vhi;
    const uint32_t* uPs  = (const uint32_t*)Ps;

    const int bh = blockIdx.y;
    const int b = bh >> 4;
    const int h = bh & 15;
    const int qt = (gridDim.x - 1) - blockIdx.x;   // heavy tiles first
    const int i0 = qt * AM;
    const float slope = (float)exp2(-0.5 * (double)(h + 1));
    const float scale = 0.08838834764831843f;      // 1/sqrt(128)

    const float* Qg = g_qkv + (size_t)bh * TT * DD;
    const float* Kg = g_qkv + ((size_t)(BB * HH) + bh) * TT * DD;
    const float* Vg = g_qkv + ((size_t)(2 * BB * HH) + bh) * TT * DD;

    const int tid = threadIdx.x;
    const int w = tid >> 5, lane = tid & 31;
    const int g = lane >> 2, c = lane & 3;
    const int r0 = w * 16;

    const int ntiles = 2 * (qt + 1);

    for (int v = tid; v < AM * 32; v += 256) {
        int r = v >> 5, c4 = (v & 31) << 2;
        cp_async16(Qs + r * QST + c4, Qg + (size_t)(i0 + r) * DD + c4);
    }
    {
        const int j0 = (ntiles - 1) * AN;
        for (int v = tid; v < AN * 32; v += 256) {
            int r = v >> 5, c4 = (v & 31) << 2;
            cp_async16(Khi[0] + r * KST + c4, Kg + (size_t)(j0 + r) * DD + c4);
        }
    }
    asm volatile("cp.async.commit_group;\n");

    float4 o[16];
#pragma unroll
    for (int i = 0; i < 16; i++) o[i] = make_float4(0.f, 0.f, 0.f, 0.f);
    float mr0 = -INFINITY, mr1 = -INFINITY, lr0 = 0.f, lr1 = 0.f;

    for (int it = 0; it < ntiles; it++) {
        const int kt2 = ntiles - 1 - it;
        const int j0 = kt2 * AN;
        const int cur = it & 1, nxt = cur ^ 1;

        const bool last = (kt2 == 0) ||
            (slope * (float)(i0 - (kt2 - 1) * AN - 63) > 24.0f);

        __syncthreads();

        for (int v = tid; v < AN * 32; v += 256) {
            int r = v >> 5, c4 = (v & 31) << 2;
            cp_async16(Vhi + r * VST + c4, Vg + (size_t)(j0 + r) * DD + c4);
        }
        asm volatile("cp.async.commit_group;\n");

        if (!last) {
            const int jn = (kt2 - 1) * AN;
            for (int v = tid; v < AN * 32; v += 256) {
                int r = v >> 5, c4 = (v & 31) << 2;
                cp_async16(Khi[nxt] + r * KST + c4, Kg + (size_t)(jn + r) * DD + c4);
            }
        }
        asm volatile("cp.async.commit_group;\n");

        asm volatile("cp.async.wait_group 2;\n");
        __syncthreads();

        const uint32_t* uKhi = (const uint32_t*)Khi[cur];
        float4 s[8];
#pragma unroll
        for (int nf = 0; nf < 8; nf++) s[nf] = make_float4(0.f, 0.f, 0.f, 0.f);
#pragma unroll 4
        for (int kc = 0; kc < 16; kc++) {
            const int k0 = kc * 8;
            uint32_t ua[4];
            ua[0] = uQs[(r0 + g)     * QST + k0 + c];
            ua[1] = uQs[(r0 + g + 8) * QST + k0 + c];
            ua[2] = uQs[(r0 + g)     * QST + k0 + c + 4];
            ua[3] = uQs[(r0 + g + 8) * QST + k0 + c + 4];
#pragma unroll
            for (int nf = 0; nf < 8; nf++) {
                uint32_t bhi[2];
                int nb = (nf * 8 + g) * KST + k0;
                bhi[0] = uKhi[nb + c]; bhi[1] = uKhi[nb + c + 4];
                mma_tf32(s[nf], ua, bhi);
            }
        }

        const int ig0 = i0 + r0 + g;
        const int ig1 = ig0 + 8;
        const bool needmask = (kt2 >= ntiles - 2);
        float tm0 = -INFINITY, tm1 = -INFINITY;
#pragma unroll
        for (int nf = 0; nf < 8; nf++) {
            int jb = j0 + nf * 8 + 2 * c;
            if (needmask) {
                s[nf].x = (jb     <= ig0) ? fmaf(slope, (float)(jb     - ig0), s[nf].x * scale) : NEGF;
                s[nf].y = (jb + 1 <= ig0) ? fmaf(slope, (float)(jb + 1 - ig0), s[nf].y * scale) : NEGF;
                s[nf].z = (jb     <= ig1) ? fmaf(slope, (float)(jb     - ig1), s[nf].z * scale) : NEGF;
                s[nf].w = (jb + 1 <= ig1) ? fmaf(slope, (float)(jb + 1 - ig1), s[nf].w * scale) : NEGF;
            } else {
                s[nf].x = fmaf(slope, (float)(jb     - ig0), s[nf].x * scale);
                s[nf].y = fmaf(slope, (float)(jb + 1 - ig0), s[nf].y * scale);
                s[nf].z = fmaf(slope, (float)(jb     - ig1), s[nf].z * scale);
                s[nf].w = fmaf(slope, (float)(jb + 1 - ig1), s[nf].w * scale);
            }
            tm0 = fmaxf(tm0, fmaxf(s[nf].x, s[nf].y));
            tm1 = fmaxf(tm1, fmaxf(s[nf].z, s[nf].w));
        }
        tm0 = fmaxf(tm0, __shfl_xor_sync(0xffffffffu, tm0, 1));
        tm0 = fmaxf(tm0, __shfl_xor_sync(0xffffffffu, tm0, 2));
        tm1 = fmaxf(tm1, __shfl_xor_sync(0xffffffffu, tm1, 1));
        tm1 = fmaxf(tm1, __shfl_xor_sync(0xffffffffu, tm1, 2));

        float mn0 = fmaxf(mr0, tm0), mn1 = fmaxf(mr1, tm1);
        float corr0 = __expf(mr0 - mn0), corr1 = __expf(mr1 - mn1);
        mr0 = mn0; mr1 = mn1;

        float rs0 = 0.f, rs1 = 0.f;
#pragma unroll
        for (int nf = 0; nf < 8; nf++) {
            float p0 = rtf(__expf(s[nf].x - mn0));
            float p1 = rtf(__expf(s[nf].y - mn0));
            float p2 = rtf(__expf(s[nf].z - mn1));
            float p3 = rtf(__expf(s[nf].w - mn1));
            rs0 += p0 + p1;
            rs1 += p2 + p3;
            *(float2*)(Ps + (r0 + g)     * PST + nf * 8 + 2 * c) = make_float2(p0, p1);
            *(float2*)(Ps + (r0 + g + 8) * PST + nf * 8 + 2 * c) = make_float2(p2, p3);
        }
        rs0 += __shfl_xor_sync(0xffffffffu, rs0, 1);
        rs0 += __shfl_xor_sync(0xffffffffu, rs0, 2);
        rs1 += __shfl_xor_sync(0xffffffffu, rs1, 1);
        rs1 += __shfl_xor_sync(0xffffffffu, rs1, 2);
        lr0 = lr0 * corr0 + rs0;
        lr1 = lr1 * corr1 + rs1;

        bool noresc = __all_sync(0xffffffffu, (corr0 == 1.0f) && (corr1 == 1.0f));
        if (!noresc) {
#pragma unroll
            for (int nf = 0; nf < 16; nf++) {
                o[nf].x *= corr0; o[nf].y *= corr0;
                o[nf].z *= corr1; o[nf].w *= corr1;
            }
        }

        asm volatile("cp.async.wait_group 1;\n");
        __syncthreads();

#pragma unroll 2
        for (int kc = 0; kc < 8; kc++) {
            const int k0 = kc * 8;
            uint32_t ua[4];
            ua[0] = uPs[(r0 + g)     * PST + k0 + c];
            ua[1] = uPs[(r0 + g + 8) * PST + k0 + c];
            ua[2] = uPs[(r0 + g)     * PST + k0 + c + 4];
            ua[3] = uPs[(r0 + g + 8) * PST + k0 + c + 4];
#pragma unroll
            for (int nf = 0; nf < 16; nf++) {
                uint32_t bhi[2];
                bhi[0] = uVhi[(k0 + c)     * VST + nf * 8 + g];
                bhi[1] = uVhi[(k0 + c + 4) * VST + nf * 8 + g];
                mma_tf32(o[nf], ua, bhi);
            }
        }

        if (last) break;
    }

    asm volatile("cp.async.wait_group 0;\n");

    // ---- epilogue: tf32 round + K-PERMUTED store into g_att ----
    float inv0 = 1.f / lr0, inv1 = 1.f / lr1;
    int t0 = i0 + r0 + g, t1 = t0 + 8;
    float* d0 = g_att + ((size_t)b * TT + t0) * CC + h * DD;
    float* d1 = g_att + ((size_t)b * TT + t1) * CC + h * DD;
#pragma unroll
    for (int nf = 0; nf < 16; nf++) {
        int colb = nf * 8 + 2 * c;                 // even, 0..126
        int hi16 = colb & ~15;
        int o2 = colb & 15;                        // even
        int a0 = hi16 + ((o2 & 3) << 2) + (o2 >> 2);
        int a1 = a0 + 4;                           // position of colb+1
        d0[a0] = rtf(o[nf].x * inv0);
        d0[a1] = rtf(o[nf].y * inv0);
        d1[a0] = rtf(o[nf].z * inv1);
        d1[a1] = rtf(o[nf].w * inv1);
    }
}

// ---------------------------------------------------------------------------
extern "C" void kernel_launch(void* const* d_in, const int* in_sizes, int n_in,
                              void* d_out, int out_size) {
    (void)in_sizes; (void)n_in; (void)out_size;
    const float* x    = (const float*)d_in[0];
    const float* Wqkv = (const float*)d_in[3];
    const float* Wout = (const float*)d_in[4];
    float* out = (float*)d_out;

    rope_table_kernel<<<TT / 4, 256>>>();

    {
        int n16 = NX16 + NQ16 + NO16;
        cvt_perm_kernel<<<(n16 + 255) / 256, 256>>>(x, Wqkv, Wout);
    }

    dim3 g1(3 * CC / 128, BB * TT / 128);   // (48, 32)
    gemm_tf32<0><<<g1, 256>>>(nullptr);

    rope_split_kernel<<<3 * BB * HH * TT / 4, 256>>>();

    cudaFuncSetAttribute(attn_mma_kernel,
                         cudaFuncAttributeMaxDynamicSharedMemorySize, ATTN_SMEM);
    dim3 g2(TT / AM, BB * HH);              // (16, 32)
    attn_mma_kernel<<<g2, 256, ATTN_SMEM>>>();

    dim3 g3(CC / 128, BB * TT / 128);       // (16, 32)
    gemm_tf32<1><<<g3, 256>>>(out);
}

// round 17
// speedup vs baseline: 1.3209x; 1.0333x over previous
#include <cuda_runtime.h>
#include <math.h>
#include <stdint.h>

#define BB 2
#define TT 2048
#define CC 2048
#define HH 16
#define DD 128
#define NEGF -1000000000.0f

// Scratch (device globals — referenced ONLY from device code)
// g_xc/g_wqc/g_woc/g_att: K-permuted within 16-blocks ((o&3)*4 + (o>>2)&3).
// g_qkv q,k slabs: D-permuted the same way (S = QK^T contracts over D, so the
// permutation cancels). v slab unpermuted.
__device__ float g_qkv[(size_t)3 * BB * HH * TT * DD];
__device__ float g_att[(size_t)BB * TT * CC];
__device__ float g_xc[(size_t)BB * TT * CC];
__device__ float g_wqc[(size_t)3 * CC * CC];
__device__ float g_woc[(size_t)CC * CC];
__device__ float g_cos[TT * 64];
__device__ float g_sin[TT * 64];

// ---------------------------------------------------------------------------
__device__ __forceinline__ uint32_t f2tf32(float x) {
    uint32_t r;
    asm volatile("cvt.rna.tf32.f32 %0, %1;\n" : "=r"(r) : "f"(x));
    return r;
}
__device__ __forceinline__ float rtf(float x) { return __uint_as_float(f2tf32(x)); }
__device__ __forceinline__ void cp_async16(void* smem, const void* gmem) {
    uint32_t s = (uint32_t)__cvta_generic_to_shared(smem);
    asm volatile("cp.async.cg.shared.global [%0], [%1], 16;\n" :: "r"(s), "l"(gmem));
}
__device__ __forceinline__ void mma_tf32(float4& d, const uint32_t a[4], const uint32_t b[2]) {
    asm volatile(
        "mma.sync.aligned.m16n8k8.row.col.f32.tf32.tf32.f32 "
        "{%0,%1,%2,%3}, {%4,%5,%6,%7}, {%8,%9}, {%0,%1,%2,%3};\n"
        : "+f"(d.x), "+f"(d.y), "+f"(d.z), "+f"(d.w)
        : "r"(a[0]), "r"(a[1]), "r"(a[2]), "r"(a[3]), "r"(b[0]), "r"(b[1]));
}
// in-16-block K permutation: original offset o -> (o&~15) | ((o&3)<<2) | ((o&15)>>2)
__device__ __forceinline__ int kperm(int o) {
    return (o & ~15) | ((o & 3) << 2) | ((o & 15) >> 2);
}

// ---------------------------------------------------------------------------
__global__ void rope_table_kernel() {   // 256 threads, 4 positions/block
    int t = blockIdx.x * 4 + (threadIdx.x >> 6);
    int d = threadIdx.x & 63;
    double inv = exp2(-((double)(2 * d) / 128.0) * log2(10000.0));
    float f = (float)t * (float)inv;
    g_cos[t * 64 + d] = cosf(f);
    g_sin[t * 64 + d] = sinf(f);
}

// Fused rounding + K-permute pass for GEMM operands.
#define NX16 (BB * TT * CC / 16)
#define NQ16 (3 * CC * CC / 16)
#define NO16 (CC * CC / 16)
__global__ void cvt_perm_kernel(const float* __restrict__ x,
                                const float* __restrict__ wq,
                                const float* __restrict__ wo) {
    int i = blockIdx.x * blockDim.x + threadIdx.x;
    const float* src; float* dst; int j;
    if (i < NX16)               { src = x;  dst = g_xc;  j = i; }
    else if (i < NX16 + NQ16)   { src = wq; dst = g_wqc; j = i - NX16; }
    else if (i < NX16 + NQ16 + NO16) { src = wo; dst = g_woc; j = i - NX16 - NQ16; }
    else return;
    const float4* s4 = (const float4*)(src + (size_t)j * 16);
    float4 i0 = s4[0], i1 = s4[1], i2 = s4[2], i3 = s4[3];
    float4* d4 = (float4*)(dst + (size_t)j * 16);
    d4[0] = make_float4(rtf(i0.x), rtf(i1.x), rtf(i2.x), rtf(i3.x));
    d4[1] = make_float4(rtf(i0.y), rtf(i1.y), rtf(i2.y), rtf(i3.y));
    d4[2] = make_float4(rtf(i0.z), rtf(i1.z), rtf(i2.z), rtf(i3.z));
    d4[3] = make_float4(rtf(i0.w), rtf(i1.w), rtf(i2.w), rtf(i3.w));
}

// ---------------------------------------------------------------------------
// RoPE + rounding, in place on g_qkv.
// q,k: rope + round, stored D-PERMUTED. v: round only, unpermuted.
// Permutation stays within 16-blocks; a 16-block never spans warps, so
// read -> __syncwarp -> write is race-free.
// ---------------------------------------------------------------------------
__global__ void rope_split_kernel() {
    int row = blockIdx.x * 4 + (threadIdx.x >> 6);
    int t = row & (TT - 1);
    int s = row >> 11;
    float* p = g_qkv + ((size_t)s * TT + t) * DD;
    int d = threadIdx.x & 63;

    if (s < 2 * BB * HH) {
        float cs = g_cos[t * 64 + d], sn = g_sin[t * 64 + d];
        float x1 = p[d], x2 = p[d + 64];
        float r1 = rtf(x1 * cs - x2 * sn);
        float r2 = rtf(x2 * cs + x1 * sn);
        __syncwarp();
        p[kperm(d)]      = r1;
        p[kperm(d + 64)] = r2;
    } else {
        p[d]      = rtf(p[d]);
        p[d + 64] = rtf(p[d + 64]);
    }
}

// ---------------------------------------------------------------------------
// tf32 mma.sync GEMM (NT), 2-stage cp.async, K-permuted operands (R16-proven,
// untouched).
// ---------------------------------------------------------------------------
#define GBK 32
#define STAGE_F (128 * GBK)

template <int EPI>
__global__ void __launch_bounds__(256, 2) gemm_tf32(float* __restrict__ out) {
    __shared__ uint32_t As[2][STAGE_F];
    __shared__ uint32_t Bs[2][STAGE_F];

    const float* A = (EPI == 0) ? (const float*)g_xc  : (const float*)g_att;
    const float* W = (EPI == 0) ? (const float*)g_wqc : (const float*)g_woc;
    const int K = CC;
    const int N = (EPI == 0) ? 3 * CC : CC;

    const int tid = threadIdx.x;
    const int m0 = blockIdx.y * 128, n0 = blockIdx.x * 128;

    const int wid = tid >> 5;
    const int lane = tid & 31;
    const int wm = wid & 3;
    const int wn = wid >> 2;
    const int g = lane >> 2;
    const int c = lane & 3;
    const int psw = (g & 1) << 2;

    const int lr = tid >> 3;
    const int lc4 = tid & 7;

    float4 acc[2][8];
#pragma unroll
    for (int i = 0; i < 2; i++)
#pragma unroll
        for (int j = 0; j < 8; j++) acc[i][j] = make_float4(0.f, 0.f, 0.f, 0.f);

    const int NT = K / GBK;

    {
#pragma unroll
        for (int i = 0; i < 4; i++) {
            int r = lr + i * 32;
            int sw = (lc4 ^ ((r & 1) << 2)) << 2;
            cp_async16(&As[0][r * GBK + sw], A + (size_t)(m0 + r) * K + lc4 * 4);
            cp_async16(&Bs[0][r * GBK + sw], W + (size_t)(n0 + r) * K + lc4 * 4);
        }
        asm volatile("cp.async.commit_group;\n");
    }

    for (int kt = 0; kt < NT; kt++) {
        int cur = kt & 1;
        if (kt + 1 < NT) {
            int nxt = cur ^ 1;
            int k0 = (kt + 1) * GBK;
#pragma unroll
            for (int i = 0; i < 4; i++) {
                int r = lr + i * 32;
                int sw = (lc4 ^ ((r & 1) << 2)) << 2;
                cp_async16(&As[nxt][r * GBK + sw], A + (size_t)(m0 + r) * K + k0 + lc4 * 4);
                cp_async16(&Bs[nxt][r * GBK + sw], W + (size_t)(n0 + r) * K + k0 + lc4 * 4);
            }
        }
        asm volatile("cp.async.commit_group;\n");
        asm volatile("cp.async.wait_group 1;\n");
        __syncthreads();

        const uint32_t* as = As[cur];
        const uint32_t* bs = Bs[cur];
#pragma unroll
        for (int p = 0; p < 2; p++) {
            const int ch = ((p * 4 + c) ^ psw) * 4;
            uint4 qa[2][2];
#pragma unroll
            for (int mf = 0; mf < 2; mf++) {
                int ra = wm * 32 + mf * 16 + g;
                qa[mf][0] = *(const uint4*)(as + ra * GBK + ch);
                qa[mf][1] = *(const uint4*)(as + (ra + 8) * GBK + ch);
            }
#pragma unroll
            for (int nf = 0; nf < 8; nf++) {
                int n = wn * 64 + nf * 8 + g;
                uint4 rb = *(const uint4*)(bs + n * GBK + ch);
                uint32_t b0[2] = { rb.x, rb.y };
                uint32_t b1[2] = { rb.z, rb.w };
#pragma unroll
                for (int mf = 0; mf < 2; mf++) {
                    uint32_t a0[4] = { qa[mf][0].x, qa[mf][1].x, qa[mf][0].y, qa[mf][1].y };
                    mma_tf32(acc[mf][nf], a0, b0);
                    uint32_t a1[4] = { qa[mf][0].z, qa[mf][1].z, qa[mf][0].w, qa[mf][1].w };
                    mma_tf32(acc[mf][nf], a1, b1);
                }
            }
        }
        __syncthreads();
    }

    if (EPI == 0) {
        const int which = n0 >> 11;
        const int hh = (n0 >> 7) & 15;
#pragma unroll
        for (int mf = 0; mf < 2; mf++) {
            int r0 = m0 + wm * 32 + mf * 16 + g;
            int b0i = r0 >> 11, t0 = r0 & 2047;
            int r1 = r0 + 8;
            int b1i = r1 >> 11, t1 = r1 & 2047;
            float* base0 = g_qkv + ((((size_t)which * BB + b0i) * HH + hh) * TT + t0) * DD;
            float* base1 = g_qkv + ((((size_t)which * BB + b1i) * HH + hh) * TT + t1) * DD;
#pragma unroll
            for (int nf = 0; nf < 8; nf++) {
                int col = wn * 64 + nf * 8 + 2 * c;
                *(float2*)(base0 + col) = make_float2(acc[mf][nf].x, acc[mf][nf].y);
                *(float2*)(base1 + col) = make_float2(acc[mf][nf].z, acc[mf][nf].w);
            }
        }
    } else {
#pragma unroll
        for (int mf = 0; mf < 2; mf++) {
            int r0 = m0 + wm * 32 + mf * 16 + g;
            int r1 = r0 + 8;
#pragma unroll
            for (int nf = 0; nf < 8; nf++) {
                int col = n0 + wn * 64 + nf * 8 + 2 * c;
                *(float2*)(out + (size_t)r0 * N + col) = make_float2(acc[mf][nf].x, acc[mf][nf].y);
                *(float2*)(out + (size_t)r1 * N + col) = make_float2(acc[mf][nf].z, acc[mf][nf].w);
            }
        }
    }
}

// ---------------------------------------------------------------------------
// Flash attention. Q/K tiles now D-permuted (S frag loads are LDS.128 with
// the GEMM's parity swizzle, stride 128). V/P paths unchanged.
// ---------------------------------------------------------------------------
#define AM 128
#define AN 64
#define QKS 128
#define VST 136
#define PST 68

#define OFF_Q   0
#define OFF_KHI (AM * QKS)                 // 16384
#define OFF_VHI (OFF_KHI + 2 * AN * QKS)   // 32768
#define OFF_P   (OFF_VHI + AN * VST)       // 41472
#define ATTN_F  (OFF_P + AM * PST)         // 50176 floats
#define ATTN_SMEM (ATTN_F * 4)             // 200704 B

__global__ void __launch_bounds__(256, 1) attn_mma_kernel() {
    extern __shared__ float sm[];
    float* Qs = sm + OFF_Q;
    float* Khi[2] = { sm + OFF_KHI, sm + OFF_KHI + AN * QKS };
    float* Vhi = sm + OFF_VHI;
    float* Ps  = sm + OFF_P;
    const uint32_t* uQs  = (const uint32_t*)Qs;
    const uint32_t* uVhi = (const uint32_t*)Vhi;
    const uint32_t* uPs  = (const uint32_t*)Ps;

    const int bh = blockIdx.y;
    const int b = bh >> 4;
    const int h = bh & 15;
    const int qt = (gridDim.x - 1) - blockIdx.x;   // heavy tiles first
    const int i0 = qt * AM;
    const float slope = (float)exp2(-0.5 * (double)(h + 1));
    const float scale = 0.08838834764831843f;      // 1/sqrt(128)

    const float* Qg = g_qkv + (size_t)bh * TT * DD;
    const float* Kg = g_qkv + ((size_t)(BB * HH) + bh) * TT * DD;
    const float* Vg = g_qkv + ((size_t)(2 * BB * HH) + bh) * TT * DD;

    const int tid = threadIdx.x;
    const int w = tid >> 5, lane = tid & 31;
    const int g = lane >> 2, c = lane & 3;
    const int psw = (g & 1) << 2;
    const int r0 = w * 16;

    const int ntiles = 2 * (qt + 1);

    // prologue: Q tile + K(diagonal), both with parity swizzle
    for (int v = tid; v < AM * 32; v += 256) {
        int r = v >> 5, ck = v & 31;
        int sw = (ck ^ ((r & 1) << 2)) << 2;
        cp_async16(Qs + r * QKS + sw, Qg + (size_t)(i0 + r) * DD + ck * 4);
    }
    {
        const int j0 = (ntiles - 1) * AN;
        for (int v = tid; v < AN * 32; v += 256) {
            int r = v >> 5, ck = v & 31;
            int sw = (ck ^ ((r & 1) << 2)) << 2;
            cp_async16(Khi[0] + r * QKS + sw, Kg + (size_t)(j0 + r) * DD + ck * 4);
        }
    }
    asm volatile("cp.async.commit_group;\n");

    float4 o[16];
#pragma unroll
    for (int i = 0; i < 16; i++) o[i] = make_float4(0.f, 0.f, 0.f, 0.f);
    float mr0 = -INFINITY, mr1 = -INFINITY, lr0 = 0.f, lr1 = 0.f;

    for (int it = 0; it < ntiles; it++) {
        const int kt2 = ntiles - 1 - it;
        const int j0 = kt2 * AN;
        const int cur = it & 1, nxt = cur ^ 1;

        const bool last = (kt2 == 0) ||
            (slope * (float)(i0 - (kt2 - 1) * AN - 63) > 24.0f);

        __syncthreads();

        // V(kt2)  [group]
        for (int v = tid; v < AN * 32; v += 256) {
            int r = v >> 5, c4 = (v & 31) << 2;
            cp_async16(Vhi + r * VST + c4, Vg + (size_t)(j0 + r) * DD + c4);
        }
        asm volatile("cp.async.commit_group;\n");

        // K(kt2-1) prefetch  [group]
        if (!last) {
            const int jn = (kt2 - 1) * AN;
            for (int v = tid; v < AN * 32; v += 256) {
                int r = v >> 5, ck = v & 31;
                int sw = (ck ^ ((r & 1) << 2)) << 2;
                cp_async16(Khi[nxt] + r * QKS + sw, Kg + (size_t)(jn + r) * DD + ck * 4);
            }
        }
        asm volatile("cp.async.commit_group;\n");

        asm volatile("cp.async.wait_group 2;\n");
        __syncthreads();

        // ---- S = Q K^T via LDS.128 frags (D-permuted operands) ----
        const uint32_t* uKhi = (const uint32_t*)Khi[cur];
        float4 s[8];
#pragma unroll
        for (int nf = 0; nf < 8; nf++) s[nf] = make_float4(0.f, 0.f, 0.f, 0.f);
#pragma unroll
        for (int sec = 0; sec < 4; sec++) {
            const uint32_t* q0p = uQs + (r0 + g) * QKS + sec * 32;
            const uint32_t* q1p = uQs + (r0 + g + 8) * QKS + sec * 32;
#pragma unroll
            for (int p = 0; p < 2; p++) {
                const int ch = ((p * 4 + c) ^ psw) * 4;
                uint4 qa0 = *(const uint4*)(q0p + ch);
                uint4 qa1 = *(const uint4*)(q1p + ch);
                uint32_t a0[4] = { qa0.x, qa1.x, qa0.y, qa1.y };
                uint32_t a1[4] = { qa0.z, qa1.z, qa0.w, qa1.w };
#pragma unroll
                for (int nf = 0; nf < 8; nf++) {
                    uint4 rb = *(const uint4*)(uKhi + (nf * 8 + g) * QKS + sec * 32 + ch);
                    uint32_t b0[2] = { rb.x, rb.y };
                    uint32_t b1[2] = { rb.z, rb.w };
                    mma_tf32(s[nf], a0, b0);
                    mma_tf32(s[nf], a1, b1);
                }
            }
        }

        // ---- scale + ALiBi (+causal mask only on diagonal tiles) ----
        const int ig0 = i0 + r0 + g;
        const int ig1 = ig0 + 8;
        const bool needmask = (kt2 >= ntiles - 2);
        float tm0 = -INFINITY, tm1 = -INFINITY;
#pragma unroll
        for (int nf = 0; nf < 8; nf++) {
            int jb = j0 + nf * 8 + 2 * c;
            if (needmask) {
                s[nf].x = (jb     <= ig0) ? fmaf(slope, (float)(jb     - ig0), s[nf].x * scale) : NEGF;
                s[nf].y = (jb + 1 <= ig0) ? fmaf(slope, (float)(jb + 1 - ig0), s[nf].y * scale) : NEGF;
                s[nf].z = (jb     <= ig1) ? fmaf(slope, (float)(jb     - ig1), s[nf].z * scale) : NEGF;
                s[nf].w = (jb + 1 <= ig1) ? fmaf(slope, (float)(jb + 1 - ig1), s[nf].w * scale) : NEGF;
            } else {
                s[nf].x = fmaf(slope, (float)(jb     - ig0), s[nf].x * scale);
                s[nf].y = fmaf(slope, (float)(jb + 1 - ig0), s[nf].y * scale);
                s[nf].z = fmaf(slope, (float)(jb     - ig1), s[nf].z * scale);
                s[nf].w = fmaf(slope, (float)(jb + 1 - ig1), s[nf].w * scale);
            }
            tm0 = fmaxf(tm0, fmaxf(s[nf].x, s[nf].y));
            tm1 = fmaxf(tm1, fmaxf(s[nf].z, s[nf].w));
        }
        tm0 = fmaxf(tm0, __shfl_xor_sync(0xffffffffu, tm0, 1));
        tm0 = fmaxf(tm0, __shfl_xor_sync(0xffffffffu, tm0, 2));
        tm1 = fmaxf(tm1, __shfl_xor_sync(0xffffffffu, tm1, 1));
        tm1 = fmaxf(tm1, __shfl_xor_sync(0xffffffffu, tm1, 2));

        float mn0 = fmaxf(mr0, tm0), mn1 = fmaxf(mr1, tm1);
        float corr0 = __expf(mr0 - mn0), corr1 = __expf(mr1 - mn1);
        mr0 = mn0; mr1 = mn1;

        float rs0 = 0.f, rs1 = 0.f;
#pragma unroll
        for (int nf = 0; nf < 8; nf++) {
            float p0 = rtf(__expf(s[nf].x - mn0));
            float p1 = rtf(__expf(s[nf].y - mn0));
            float p2 = rtf(__expf(s[nf].z - mn1));
            float p3 = rtf(__expf(s[nf].w - mn1));
            rs0 += p0 + p1;
            rs1 += p2 + p3;
            *(float2*)(Ps + (r0 + g)     * PST + nf * 8 + 2 * c) = make_float2(p0, p1);
            *(float2*)(Ps + (r0 + g + 8) * PST + nf * 8 + 2 * c) = make_float2(p2, p3);
        }
        rs0 += __shfl_xor_sync(0xffffffffu, rs0, 1);
        rs0 += __shfl_xor_sync(0xffffffffu, rs0, 2);
        rs1 += __shfl_xor_sync(0xffffffffu, rs1, 1);
        rs1 += __shfl_xor_sync(0xffffffffu, rs1, 2);
        lr0 = lr0 * corr0 + rs0;
        lr1 = lr1 * corr1 + rs1;

        bool noresc = __all_sync(0xffffffffu, (corr0 == 1.0f) && (corr1 == 1.0f));
        if (!noresc) {
#pragma unroll
            for (int nf = 0; nf < 16; nf++) {
                o[nf].x *= corr0; o[nf].y *= corr0;
                o[nf].z *= corr1; o[nf].w *= corr1;
            }
        }

        asm volatile("cp.async.wait_group 1;\n");
        __syncthreads();

        // ---- O += P * Vhi (single pass) ----
#pragma unroll 2
        for (int kc = 0; kc < 8; kc++) {
            const int k0 = kc * 8;
            uint32_t ua[4];
            ua[0] = uPs[(r0 + g)     * PST + k0 + c];
            ua[1] = uPs[(r0 + g + 8) * PST + k0 + c];
            ua[2] = uPs[(r0 + g)     * PST + k0 + c + 4];
            ua[3] = uPs[(r0 + g + 8) * PST + k0 + c + 4];
#pragma unroll
            for (int nf = 0; nf < 16; nf++) {
                uint32_t bhi[2];
                bhi[0] = uVhi[(k0 + c)     * VST + nf * 8 + g];
                bhi[1] = uVhi[(k0 + c + 4) * VST + nf * 8 + g];
                mma_tf32(o[nf], ua, bhi);
            }
        }

        if (last) break;
    }

    asm volatile("cp.async.wait_group 0;\n");

    // ---- epilogue: tf32 round + K-PERMUTED store into g_att ----
    float inv0 = 1.f / lr0, inv1 = 1.f / lr1;
    int t0 = i0 + r0 + g, t1 = t0 + 8;
    float* d0 = g_att + ((size_t)b * TT + t0) * CC + h * DD;
    float* d1 = g_att + ((size_t)b * TT + t1) * CC + h * DD;
#pragma unroll
    for (int nf = 0; nf < 16; nf++) {
        int colb = nf * 8 + 2 * c;
        int a0 = kperm(colb);
        int a1 = a0 + 4;
        d0[a0] = rtf(o[nf].x * inv0);
        d0[a1] = rtf(o[nf].y * inv0);
        d1[a0] = rtf(o[nf].z * inv1);
        d1[a1] = rtf(o[nf].w * inv1);
    }
}

// ---------------------------------------------------------------------------
extern "C" void kernel_launch(void* const* d_in, const int* in_sizes, int n_in,
                              void* d_out, int out_size) {
    (void)in_sizes; (void)n_in; (void)out_size;
    const float* x    = (const float*)d_in[0];
    const float* Wqkv = (const float*)d_in[3];
    const float* Wout = (const float*)d_in[4];
    float* out = (float*)d_out;

    rope_table_kernel<<<TT / 4, 256>>>();

    {
        int n16 = NX16 + NQ16 + NO16;
        cvt_perm_kernel<<<(n16 + 255) / 256, 256>>>(x, Wqkv, Wout);
    }

    dim3 g1(3 * CC / 128, BB * TT / 128);   // (48, 32)
    gemm_tf32<0><<<g1, 256>>>(nullptr);

    rope_split_kernel<<<3 * BB * HH * TT / 4, 256>>>();

    cudaFuncSetAttribute(attn_mma_kernel,
                         cudaFuncAttributeMaxDynamicSharedMemorySize, ATTN_SMEM);
    dim3 g2(TT / AM, BB * HH);              // (16, 32)
    attn_mma_kernel<<<g2, 256, ATTN_SMEM>>>();

    dim3 g3(CC / 128, BB * TT / 128);       // (16, 32)
    gemm_tf32<1><<<g3, 256>>>(out);
}